// round 1
// baseline (speedup 1.0000x reference)
#include <cuda_runtime.h>
#include <cuda_bf16.h>

#define N_NODES 100000
#define N_EDGES 3200000
#define N_GRAPHS 4096
#define IN_DIM 128
#define HID 64
#define EPS 1e-5f

// ---------------- scratch (device globals; no allocation) ----------------
__device__ float d_gbuf[N_NODES * HID];   // messages g = dinv * (h @ W)
__device__ float d_acc [N_NODES * HID];   // scatter accumulator (init = g for self loop)
__device__ int   d_deg [N_NODES];
__device__ float d_dinv[N_NODES];
__device__ float d_stat[4 * 2 * HID];     // per "layer" L in 0..3: [L*128 + f]=sum, [L*128+64+f]=sumsq
__device__ float d_st  [4 * 2 * HID];     // per layer: [L*128+f]=scale s, [L*128+64+f]=shift t
__device__ float d_pool[N_GRAPHS * HID];
__device__ float d_pcnt[N_GRAPHS];
__device__ float d_q   [N_GRAPHS * HID];

// ---------------- helpers ----------------
__device__ __forceinline__ void red_add_v4(float* addr, float4 v) {
    unsigned long long p = (unsigned long long)__cvta_generic_to_global(addr);
    asm volatile("red.global.add.v4.f32 [%0], {%1,%2,%3,%4};"
                 :: "l"(p), "f"(v.x), "f"(v.y), "f"(v.z), "f"(v.w) : "memory");
}

// ---------------- kernels ----------------
__global__ void k_init() {
    int idx = blockIdx.x * blockDim.x + threadIdx.x;
    int stride = gridDim.x * blockDim.x;
    for (int i = idx; i < N_NODES; i += stride) d_deg[i] = 1;           // self loop
    for (int i = idx; i < 4 * 2 * HID; i += stride) d_stat[i] = 0.f;
    for (int i = idx; i < N_GRAPHS * HID; i += stride) d_pool[i] = 0.f;
    for (int i = idx; i < N_GRAPHS; i += stride) d_pcnt[i] = 0.f;
}

__global__ void k_deg(const int* __restrict__ col) {
    int idx = blockIdx.x * blockDim.x + threadIdx.x;
    int stride = gridDim.x * blockDim.x;
    for (int e = idx; e < N_EDGES; e += stride)
        atomicAdd(&d_deg[col[e]], 1);
}

__global__ void k_dinv() {
    int i = blockIdx.x * blockDim.x + threadIdx.x;
    if (i < N_NODES) d_dinv[i] = rsqrtf((float)d_deg[i]);
}

// GEMM: out[n][f] = dinv[n] * sum_k inp[n][k] * W[k][f]
// TRANS: inp is d_acc of previous layer, transformed on load:
//   v = relu( (acc*dinv) * s[k] + t[k] )   (BN+relu fused; bias cancels in BN)
// Writes both d_gbuf and d_acc (acc init = self-loop message).
template <int KT, bool TRANS>
__global__ void k_gemm(const float* __restrict__ in, const float* __restrict__ W, int stL) {
    __shared__ float sW[64 * 64];
    __shared__ float sIn[64 * 64];
    const int f  = threadIdx.x & 63;
    const int nr = threadIdx.x >> 6;            // 0..3
    const int base = blockIdx.x * 64;
    const int K = KT * 64;
    const float* sv = d_st + stL * 128;

    float acc[16];
#pragma unroll
    for (int i = 0; i < 16; i++) acc[i] = 0.f;

    for (int kt = 0; kt < KT; kt++) {
        for (int i = threadIdx.x; i < 64 * 64; i += 256)
            sW[i] = W[kt * 4096 + i];
        for (int i = threadIdx.x; i < 64 * 64; i += 256) {
            int n = i >> 6, k = i & 63;
            int ng = base + n;
            float v = 0.f;
            if (ng < N_NODES) {
                if (TRANS) {
                    float y = d_acc[ng * 64 + k] * d_dinv[ng];
                    v = fmaxf(fmaf(y, sv[k], sv[64 + k]), 0.f);
                } else {
                    v = in[ng * K + kt * 64 + k];
                }
            }
            sIn[i] = v;
        }
        __syncthreads();
#pragma unroll 8
        for (int kk = 0; kk < 64; kk++) {
            float wv = sW[kk * 64 + f];
#pragma unroll
            for (int i = 0; i < 16; i++)
                acc[i] = fmaf(sIn[(nr + 4 * i) * 64 + kk], wv, acc[i]);
        }
        __syncthreads();
    }
#pragma unroll
    for (int i = 0; i < 16; i++) {
        int n = base + nr + 4 * i;
        if (n < N_NODES) {
            float o = acc[i] * d_dinv[n];
            d_gbuf[n * 64 + f] = o;
            d_acc [n * 64 + f] = o;     // self-loop contribution
        }
    }
}

// Scatter: acc[col] += g[row], 16 lanes/edge, vector reductions.
__global__ void k_aggr(const int* __restrict__ row, const int* __restrict__ col) {
    int t = blockIdx.x * blockDim.x + threadIdx.x;
    int lane = t & 15;
    int e = t >> 4;
    if (e >= N_EDGES) return;
    int r = row[e];
    int c = col[e];
    float4 v = *reinterpret_cast<const float4*>(&d_gbuf[r * 64 + lane * 4]);
    red_add_v4(&d_acc[c * 64 + lane * 4], v);
}

// Per-feature sum / sumsq of y = acc * dinv  (for BN over nodes)
__global__ void k_stats(int L) {
    __shared__ float ssum[256], ssq[256];
    int f = threadIdx.x & 63, r = threadIdx.x >> 6;
    float sum = 0.f, sq = 0.f;
    for (int n = blockIdx.x * 4 + r; n < N_NODES; n += gridDim.x * 4) {
        float y = d_acc[n * 64 + f] * d_dinv[n];
        sum += y; sq += y * y;
    }
    ssum[threadIdx.x] = sum; ssq[threadIdx.x] = sq;
    __syncthreads();
    if (r == 0) {
        sum = ssum[f] + ssum[f + 64] + ssum[f + 128] + ssum[f + 192];
        sq  = ssq [f] + ssq [f + 64] + ssq [f + 128] + ssq [f + 192];
        atomicAdd(&d_stat[L * 128 + f], sum);
        atomicAdd(&d_stat[L * 128 + 64 + f], sq);
    }
}

// Finalize BN: s = gamma*rsqrt(var+eps), t = beta - mean*s  (conv bias cancels)
__global__ void k_fin(int L, const float* __restrict__ g, const float* __restrict__ be, float cnt) {
    int f = threadIdx.x;
    float mean = d_stat[L * 128 + f] / cnt;
    float var  = d_stat[L * 128 + 64 + f] / cnt - mean * mean;
    var = fmaxf(var, 0.f);
    float s = g[f] * rsqrtf(var + EPS);
    d_st[L * 128 + f] = s;
    d_st[L * 128 + 64 + f] = be[f] - mean * s;
}

// Apply layer-2 BN+relu and scatter mean-pool sums per graph.
__global__ void k_pool(const int* __restrict__ batch) {
    int t = blockIdx.x * blockDim.x + threadIdx.x;
    int lane = t & 15;
    int n = t >> 4;
    if (n >= N_NODES) return;
    int b = batch[n];
    float dv = d_dinv[n];
    const float* s = d_st + 2 * 128;
    float4 a = *reinterpret_cast<const float4*>(&d_acc[n * 64 + lane * 4]);
    float4 z;
    z.x = fmaxf(fmaf(a.x * dv, s[lane * 4 + 0], s[64 + lane * 4 + 0]), 0.f);
    z.y = fmaxf(fmaf(a.y * dv, s[lane * 4 + 1], s[64 + lane * 4 + 1]), 0.f);
    z.z = fmaxf(fmaf(a.z * dv, s[lane * 4 + 2], s[64 + lane * 4 + 2]), 0.f);
    z.w = fmaxf(fmaf(a.w * dv, s[lane * 4 + 3], s[64 + lane * 4 + 3]), 0.f);
    red_add_v4(&d_pool[b * 64 + lane * 4], z);
    if (lane == 0) atomicAdd(&d_pcnt[b], 1.0f);
}

// pooled @ W1 (b1 cancels in BN) + accumulate FC BN stats
__global__ void k_fc1(const float* __restrict__ W1) {
    __shared__ float sp[64];
    int gidx = blockIdx.x, f = threadIdx.x;
    float cnt = fmaxf(d_pcnt[gidx], 1.f);
    sp[f] = d_pool[gidx * 64 + f] / cnt;
    __syncthreads();
    float q = 0.f;
#pragma unroll 8
    for (int k = 0; k < 64; k++)
        q = fmaf(sp[k], __ldg(&W1[k * 64 + f]), q);
    d_q[gidx * 64 + f] = q;
    atomicAdd(&d_stat[3 * 128 + f], q);
    atomicAdd(&d_stat[3 * 128 + 64 + f], q * q);
}

// relu(BN(q)) @ W2 + b2
__global__ void k_fc2(const float* __restrict__ W2, const float* __restrict__ b2,
                      float* __restrict__ out) {
    int g = blockIdx.x * (blockDim.x / 32) + (threadIdx.x >> 5);
    int lane = threadIdx.x & 31;
    if (g >= N_GRAPHS) return;
    const float* s = d_st + 3 * 128;
    float acc = 0.f;
#pragma unroll
    for (int j = 0; j < 2; j++) {
        int f = lane + 32 * j;
        float z = fmaxf(fmaf(d_q[g * 64 + f], s[f], s[64 + f]), 0.f);
        acc = fmaf(z, W2[f], acc);
    }
#pragma unroll
    for (int o = 16; o > 0; o >>= 1)
        acc += __shfl_down_sync(0xffffffffu, acc, o);
    if (lane == 0) out[g] = acc + b2[0];
}

// ---------------- launch ----------------
extern "C" void kernel_launch(void* const* d_in, const int* in_sizes, int n_in,
                              void* d_out, int out_size) {
    const float* x     = (const float*)d_in[0];
    const int*   ei    = (const int*)d_in[1];
    const int*   row   = ei;
    const int*   col   = ei + N_EDGES;
    const int*   batch = (const int*)d_in[2];
    const float* Wc0 = (const float*)d_in[3];
    const float* g0  = (const float*)d_in[5];
    const float* be0 = (const float*)d_in[6];
    const float* Wc1 = (const float*)d_in[7];
    const float* g1  = (const float*)d_in[9];
    const float* be1 = (const float*)d_in[10];
    const float* Wc2 = (const float*)d_in[11];
    const float* g2  = (const float*)d_in[13];
    const float* be2 = (const float*)d_in[14];
    const float* W1  = (const float*)d_in[15];
    const float* gf  = (const float*)d_in[17];
    const float* bf  = (const float*)d_in[18];
    const float* W2  = (const float*)d_in[19];
    const float* b2  = (const float*)d_in[20];
    float* out = (float*)d_out;

    const int GEMM_GRID = (N_NODES + 63) / 64;             // 1563
    const int AGGR_GRID = (N_EDGES * 16) / 256;            // 200000 (exact)
    const int POOL_GRID = (N_NODES * 16 + 255) / 256;      // 6250

    k_init<<<1024, 256>>>();
    k_deg <<<8192, 256>>>(col);
    k_dinv<<<(N_NODES + 255) / 256, 256>>>();

    // layer 0
    k_gemm<2, false><<<GEMM_GRID, 256>>>(x, Wc0, 0);
    k_aggr<<<AGGR_GRID, 256>>>(row, col);
    k_stats<<<256, 256>>>(0);
    k_fin<<<1, 64>>>(0, g0, be0, (float)N_NODES);

    // layer 1
    k_gemm<1, true><<<GEMM_GRID, 256>>>(x, Wc1, 0);
    k_aggr<<<AGGR_GRID, 256>>>(row, col);
    k_stats<<<256, 256>>>(1);
    k_fin<<<1, 64>>>(1, g1, be1, (float)N_NODES);

    // layer 2
    k_gemm<1, true><<<GEMM_GRID, 256>>>(x, Wc2, 1);
    k_aggr<<<AGGR_GRID, 256>>>(row, col);
    k_stats<<<256, 256>>>(2);
    k_fin<<<1, 64>>>(2, g2, be2, (float)N_NODES);

    // pooling + head
    k_pool<<<POOL_GRID, 256>>>(batch);
    k_fc1<<<N_GRAPHS, 64>>>(W1);
    k_fin<<<1, 64>>>(3, gf, bf, (float)N_GRAPHS);
    k_fc2<<<N_GRAPHS / 8, 256>>>(W2, b2, out);
}

// round 2
// speedup vs baseline: 1.5347x; 1.5347x over previous
#include <cuda_runtime.h>
#include <cuda_bf16.h>

#define N_NODES 100000
#define N_EDGES 3200000
#define N_GRAPHS 4096
#define IN_DIM 128
#define HID 64
#define EPS 1e-5f

#define SCAN_B 512
#define NBLK ((N_NODES + SCAN_B - 1) / SCAN_B)   // 196

// ---------------- scratch (device globals; no allocation) ----------------
__device__ float d_gbuf[N_NODES * HID];   // messages g = dinv * (h @ W)
__device__ float d_acc [N_NODES * HID];   // conv output y (post-dinv, pre-BN)
__device__ int   d_deg [N_NODES];
__device__ float d_dinv[N_NODES];
__device__ int   d_off [N_NODES];         // CSR offsets (exclusive scan of in-degree)
__device__ int   d_cur [N_NODES];         // atomic cursors for fill
__device__ int   d_bsum[NBLK];
__device__ int   d_csr [N_EDGES];         // row ids grouped by col
__device__ float d_stat[4 * 2 * HID];
__device__ float d_st  [4 * 2 * HID];
__device__ float d_pool[N_GRAPHS * HID];
__device__ float d_pcnt[N_GRAPHS];
__device__ float d_q   [N_GRAPHS * HID];

__device__ __forceinline__ void red_add_v4(float* addr, float4 v) {
    unsigned long long p = (unsigned long long)__cvta_generic_to_global(addr);
    asm volatile("red.global.add.v4.f32 [%0], {%1,%2,%3,%4};"
                 :: "l"(p), "f"(v.x), "f"(v.y), "f"(v.z), "f"(v.w) : "memory");
}

// ---------------- setup kernels ----------------
__global__ void k_init() {
    int idx = blockIdx.x * blockDim.x + threadIdx.x;
    int stride = gridDim.x * blockDim.x;
    for (int i = idx; i < N_NODES; i += stride) d_deg[i] = 1;           // self loop
    for (int i = idx; i < 4 * 2 * HID; i += stride) d_stat[i] = 0.f;
    for (int i = idx; i < N_GRAPHS * HID; i += stride) d_pool[i] = 0.f;
    for (int i = idx; i < N_GRAPHS; i += stride) d_pcnt[i] = 0.f;
}

__global__ void k_deg(const int* __restrict__ col) {
    int idx = blockIdx.x * blockDim.x + threadIdx.x;
    int stride = gridDim.x * blockDim.x;
    for (int e = idx; e < N_EDGES; e += stride)
        atomicAdd(&d_deg[col[e]], 1);
}

__global__ void k_dinv() {
    int i = blockIdx.x * blockDim.x + threadIdx.x;
    if (i < N_NODES) d_dinv[i] = rsqrtf((float)d_deg[i]);
}

// exclusive scan of in-degree (deg-1), 3 phases
__global__ void k_scanA() {
    __shared__ int s[SCAN_B];
    int i = blockIdx.x * SCAN_B + threadIdx.x;
    int v = (i < N_NODES) ? d_deg[i] - 1 : 0;
    s[threadIdx.x] = v;
    __syncthreads();
    for (int off = 1; off < SCAN_B; off <<= 1) {
        int t = (threadIdx.x >= off) ? s[threadIdx.x - off] : 0;
        __syncthreads();
        s[threadIdx.x] += t;
        __syncthreads();
    }
    if (i < N_NODES) d_off[i] = s[threadIdx.x] - v;
    if (threadIdx.x == SCAN_B - 1) d_bsum[blockIdx.x] = s[SCAN_B - 1];
}

__global__ void k_scanB() {
    __shared__ int s[256];
    int v = (threadIdx.x < NBLK) ? d_bsum[threadIdx.x] : 0;
    s[threadIdx.x] = v;
    __syncthreads();
    for (int off = 1; off < 256; off <<= 1) {
        int t = (threadIdx.x >= off) ? s[threadIdx.x - off] : 0;
        __syncthreads();
        s[threadIdx.x] += t;
        __syncthreads();
    }
    if (threadIdx.x < NBLK) d_bsum[threadIdx.x] = s[threadIdx.x] - v;
}

__global__ void k_scanC() {
    int i = blockIdx.x * blockDim.x + threadIdx.x;
    if (i < N_NODES) {
        int o = d_off[i] + d_bsum[i / SCAN_B];
        d_off[i] = o;
        d_cur[i] = o;
    }
}

__global__ void k_fill(const int* __restrict__ row, const int* __restrict__ col) {
    int idx = blockIdx.x * blockDim.x + threadIdx.x;
    int stride = gridDim.x * blockDim.x;
    for (int e = idx; e < N_EDGES; e += stride) {
        int pos = atomicAdd(&d_cur[col[e]], 1);
        d_csr[pos] = row[e];
    }
}

// ---------------- GEMM: gbuf[n][f] = dinv[n] * sum_k inp[n][k] * W[k][f] ----
// TRANS: input is d_acc (= y of prev layer): v = relu(y*s[k] + t[k])
template <int KT, bool TRANS>
__global__ void k_gemm(const float* __restrict__ in, const float* __restrict__ W, int stL) {
    __shared__ float sW[64 * 64];       // sW[k][f]
    __shared__ float sX[64 * 68];       // sX[k][n], padded stride 68
    const int tr = threadIdx.x & 15;    // rows tr*4 .. tr*4+3
    const int tc = threadIdx.x >> 4;    // cols tc*4 .. tc*4+3
    const int base = blockIdx.x * 64;
    const float* sv = d_st + stL * 128;

    float acc[4][4];
#pragma unroll
    for (int i = 0; i < 4; i++)
#pragma unroll
        for (int j = 0; j < 4; j++) acc[i][j] = 0.f;

    for (int kt = 0; kt < KT; kt++) {
        for (int i = threadIdx.x; i < 4096; i += 256)
            sW[i] = W[kt * 4096 + i];
        for (int i = threadIdx.x; i < 4096; i += 256) {
            int n = i >> 6, k = i & 63;
            int ng = base + n;
            float v = 0.f;
            if (ng < N_NODES) {
                if (TRANS) v = fmaxf(fmaf(d_acc[ng * 64 + k], sv[k], sv[64 + k]), 0.f);
                else       v = in[ng * (KT * 64) + kt * 64 + k];
            }
            sX[k * 68 + n] = v;
        }
        __syncthreads();
#pragma unroll 8
        for (int kk = 0; kk < 64; kk++) {
            float4 xv = *reinterpret_cast<float4*>(&sX[kk * 68 + tr * 4]);
            float4 wv = *reinterpret_cast<float4*>(&sW[kk * 64 + tc * 4]);
            acc[0][0] = fmaf(xv.x, wv.x, acc[0][0]);
            acc[0][1] = fmaf(xv.x, wv.y, acc[0][1]);
            acc[0][2] = fmaf(xv.x, wv.z, acc[0][2]);
            acc[0][3] = fmaf(xv.x, wv.w, acc[0][3]);
            acc[1][0] = fmaf(xv.y, wv.x, acc[1][0]);
            acc[1][1] = fmaf(xv.y, wv.y, acc[1][1]);
            acc[1][2] = fmaf(xv.y, wv.z, acc[1][2]);
            acc[1][3] = fmaf(xv.y, wv.w, acc[1][3]);
            acc[2][0] = fmaf(xv.z, wv.x, acc[2][0]);
            acc[2][1] = fmaf(xv.z, wv.y, acc[2][1]);
            acc[2][2] = fmaf(xv.z, wv.z, acc[2][2]);
            acc[2][3] = fmaf(xv.z, wv.w, acc[2][3]);
            acc[3][0] = fmaf(xv.w, wv.x, acc[3][0]);
            acc[3][1] = fmaf(xv.w, wv.y, acc[3][1]);
            acc[3][2] = fmaf(xv.w, wv.z, acc[3][2]);
            acc[3][3] = fmaf(xv.w, wv.w, acc[3][3]);
        }
        __syncthreads();
    }
#pragma unroll
    for (int i = 0; i < 4; i++) {
        int n = base + tr * 4 + i;
        if (n < N_NODES) {
            float dv = d_dinv[n];
            float4 o = make_float4(acc[i][0] * dv, acc[i][1] * dv,
                                   acc[i][2] * dv, acc[i][3] * dv);
            *reinterpret_cast<float4*>(&d_gbuf[n * 64 + tc * 4]) = o;
        }
    }
}

// ---------------- CSR gather-aggregate: one warp per node -------------------
// y[c] = dinv[c] * ( sum_{e: col=c} gbuf[row_e] + gbuf[c] )  -> d_acc
__global__ void k_aggr2() {
    int node = (blockIdx.x * blockDim.x + threadIdx.x) >> 5;
    int lane = threadIdx.x & 31;
    if (node >= N_NODES) return;
    int start = d_off[node];
    int deg = d_deg[node] - 1;
    const float2* gb = reinterpret_cast<const float2*>(d_gbuf);

    float2 a0 = {0.f, 0.f}, a1 = {0.f, 0.f}, a2 = {0.f, 0.f}, a3 = {0.f, 0.f};
    for (int base = 0; base < deg; base += 32) {
        int rem = deg - base; if (rem > 32) rem = 32;
        int id = (lane < rem) ? __ldg(&d_csr[start + base + lane]) : 0;
        int j = 0;
        for (; j + 4 <= rem; j += 4) {
            int r0 = __shfl_sync(0xffffffffu, id, j);
            int r1 = __shfl_sync(0xffffffffu, id, j + 1);
            int r2 = __shfl_sync(0xffffffffu, id, j + 2);
            int r3 = __shfl_sync(0xffffffffu, id, j + 3);
            float2 v0 = gb[r0 * 32 + lane];
            float2 v1 = gb[r1 * 32 + lane];
            float2 v2 = gb[r2 * 32 + lane];
            float2 v3 = gb[r3 * 32 + lane];
            a0.x += v0.x; a0.y += v0.y;
            a1.x += v1.x; a1.y += v1.y;
            a2.x += v2.x; a2.y += v2.y;
            a3.x += v3.x; a3.y += v3.y;
        }
        for (; j < rem; j++) {
            int r = __shfl_sync(0xffffffffu, id, j);
            float2 v = gb[r * 32 + lane];
            a0.x += v.x; a0.y += v.y;
        }
    }
    float2 self = gb[node * 32 + lane];
    float dv = d_dinv[node];
    float2 y;
    y.x = (a0.x + a1.x + a2.x + a3.x + self.x) * dv;
    y.y = (a0.y + a1.y + a2.y + a3.y + self.y) * dv;
    reinterpret_cast<float2*>(d_acc)[node * 32 + lane] = y;
}

// ---------------- BN stats over nodes (y = d_acc directly) ------------------
__global__ void k_stats(int L) {
    __shared__ float ssum[256], ssq[256];
    int f = threadIdx.x & 63, r = threadIdx.x >> 6;
    float sum = 0.f, sq = 0.f;
    for (int n = blockIdx.x * 4 + r; n < N_NODES; n += gridDim.x * 4) {
        float y = d_acc[n * 64 + f];
        sum += y; sq += y * y;
    }
    ssum[threadIdx.x] = sum; ssq[threadIdx.x] = sq;
    __syncthreads();
    if (r == 0) {
        sum = ssum[f] + ssum[f + 64] + ssum[f + 128] + ssum[f + 192];
        sq  = ssq [f] + ssq [f + 64] + ssq [f + 128] + ssq [f + 192];
        atomicAdd(&d_stat[L * 128 + f], sum);
        atomicAdd(&d_stat[L * 128 + 64 + f], sq);
    }
}

__global__ void k_fin(int L, const float* __restrict__ g, const float* __restrict__ be, float cnt) {
    int f = threadIdx.x;
    float mean = d_stat[L * 128 + f] / cnt;
    float var  = d_stat[L * 128 + 64 + f] / cnt - mean * mean;
    var = fmaxf(var, 0.f);
    float s = g[f] * rsqrtf(var + EPS);
    d_st[L * 128 + f] = s;
    d_st[L * 128 + 64 + f] = be[f] - mean * s;
}

// ---------------- pooling + head ----------------
__global__ void k_pool(const int* __restrict__ batch) {
    int t = blockIdx.x * blockDim.x + threadIdx.x;
    int lane = t & 15;
    int n = t >> 4;
    if (n >= N_NODES) return;
    int b = batch[n];
    const float* s = d_st + 2 * 128;
    float4 a = *reinterpret_cast<const float4*>(&d_acc[n * 64 + lane * 4]);
    float4 z;
    z.x = fmaxf(fmaf(a.x, s[lane * 4 + 0], s[64 + lane * 4 + 0]), 0.f);
    z.y = fmaxf(fmaf(a.y, s[lane * 4 + 1], s[64 + lane * 4 + 1]), 0.f);
    z.z = fmaxf(fmaf(a.z, s[lane * 4 + 2], s[64 + lane * 4 + 2]), 0.f);
    z.w = fmaxf(fmaf(a.w, s[lane * 4 + 3], s[64 + lane * 4 + 3]), 0.f);
    red_add_v4(&d_pool[b * 64 + lane * 4], z);
    if (lane == 0) atomicAdd(&d_pcnt[b], 1.0f);
}

__global__ void k_fc1(const float* __restrict__ W1) {
    __shared__ float sp[64];
    int gidx = blockIdx.x, f = threadIdx.x;
    float cnt = fmaxf(d_pcnt[gidx], 1.f);
    sp[f] = d_pool[gidx * 64 + f] / cnt;
    __syncthreads();
    float q = 0.f;
#pragma unroll 8
    for (int k = 0; k < 64; k++)
        q = fmaf(sp[k], __ldg(&W1[k * 64 + f]), q);
    d_q[gidx * 64 + f] = q;
    atomicAdd(&d_stat[3 * 128 + f], q);
    atomicAdd(&d_stat[3 * 128 + 64 + f], q * q);
}

__global__ void k_fc2(const float* __restrict__ W2, const float* __restrict__ b2,
                      float* __restrict__ out) {
    int g = blockIdx.x * (blockDim.x / 32) + (threadIdx.x >> 5);
    int lane = threadIdx.x & 31;
    if (g >= N_GRAPHS) return;
    const float* s = d_st + 3 * 128;
    float acc = 0.f;
#pragma unroll
    for (int j = 0; j < 2; j++) {
        int f = lane + 32 * j;
        float z = fmaxf(fmaf(d_q[g * 64 + f], s[f], s[64 + f]), 0.f);
        acc = fmaf(z, W2[f], acc);
    }
#pragma unroll
    for (int o = 16; o > 0; o >>= 1)
        acc += __shfl_down_sync(0xffffffffu, acc, o);
    if (lane == 0) out[g] = acc + b2[0];
}

// ---------------- launch ----------------
extern "C" void kernel_launch(void* const* d_in, const int* in_sizes, int n_in,
                              void* d_out, int out_size) {
    const float* x     = (const float*)d_in[0];
    const int*   ei    = (const int*)d_in[1];
    const int*   row   = ei;
    const int*   col   = ei + N_EDGES;
    const int*   batch = (const int*)d_in[2];
    const float* Wc0 = (const float*)d_in[3];
    const float* g0  = (const float*)d_in[5];
    const float* be0 = (const float*)d_in[6];
    const float* Wc1 = (const float*)d_in[7];
    const float* g1  = (const float*)d_in[9];
    const float* be1 = (const float*)d_in[10];
    const float* Wc2 = (const float*)d_in[11];
    const float* g2  = (const float*)d_in[13];
    const float* be2 = (const float*)d_in[14];
    const float* W1  = (const float*)d_in[15];
    const float* gf  = (const float*)d_in[17];
    const float* bf  = (const float*)d_in[18];
    const float* W2  = (const float*)d_in[19];
    const float* b2  = (const float*)d_in[20];
    float* out = (float*)d_out;

    const int GEMM_GRID = (N_NODES + 63) / 64;              // 1563
    const int AGGR_GRID = (N_NODES * 32 + 255) / 256;       // 12500
    const int POOL_GRID = (N_NODES * 16 + 255) / 256;       // 6250

    k_init<<<1024, 256>>>();
    k_deg <<<8192, 256>>>(col);
    k_dinv<<<(N_NODES + 255) / 256, 256>>>();
    k_scanA<<<NBLK, SCAN_B>>>();
    k_scanB<<<1, 256>>>();
    k_scanC<<<(N_NODES + 255) / 256, 256>>>();
    k_fill<<<8192, 256>>>(row, col);

    // layer 0
    k_gemm<2, false><<<GEMM_GRID, 256>>>(x, Wc0, 0);
    k_aggr2<<<AGGR_GRID, 256>>>();
    k_stats<<<256, 256>>>(0);
    k_fin<<<1, 64>>>(0, g0, be0, (float)N_NODES);

    // layer 1
    k_gemm<1, true><<<GEMM_GRID, 256>>>(x, Wc1, 0);
    k_aggr2<<<AGGR_GRID, 256>>>();
    k_stats<<<256, 256>>>(1);
    k_fin<<<1, 64>>>(1, g1, be1, (float)N_NODES);

    // layer 2
    k_gemm<1, true><<<GEMM_GRID, 256>>>(x, Wc2, 1);
    k_aggr2<<<AGGR_GRID, 256>>>();
    k_stats<<<256, 256>>>(2);
    k_fin<<<1, 64>>>(2, g2, be2, (float)N_NODES);

    // pooling + head
    k_pool<<<POOL_GRID, 256>>>(batch);
    k_fc1<<<N_GRAPHS, 64>>>(W1);
    k_fin<<<1, 64>>>(3, gf, bf, (float)N_GRAPHS);
    k_fc2<<<N_GRAPHS / 8, 256>>>(W2, b2, out);
}

// round 3
// speedup vs baseline: 1.6730x; 1.0901x over previous
#include <cuda_runtime.h>
#include <cuda_bf16.h>

#define N_NODES 100000
#define N_EDGES 3200000
#define N_GRAPHS 4096
#define IN_DIM 128
#define HID 64
#define EPS 1e-5f

#define SCAN_B 512
#define NBLK ((N_NODES + SCAN_B - 1) / SCAN_B)   // 196

// ---------------- scratch (device globals; no allocation) ----------------
__device__ float d_gbuf[N_NODES * HID];   // messages (layer0: h; layers1/2: dinv*h)
__device__ float d_acc [N_NODES * HID];   // conv output y (post-dinv, pre-BN)
__device__ int   d_deg [N_NODES];
__device__ float d_dinv[N_NODES];
__device__ int   d_off [N_NODES];
__device__ int   d_cur [N_NODES];
__device__ int   d_bsum[NBLK];
__device__ int   d_csr [N_EDGES];
__device__ float d_stat[4 * 2 * HID];
__device__ float d_st  [4 * 2 * HID];
__device__ float d_pool[N_GRAPHS * HID];
__device__ float d_pcnt[N_GRAPHS];
__device__ float d_q   [N_GRAPHS * HID];

__device__ __forceinline__ void red_add_v4(float* addr, float4 v) {
    unsigned long long p = (unsigned long long)__cvta_generic_to_global(addr);
    asm volatile("red.global.add.v4.f32 [%0], {%1,%2,%3,%4};"
                 :: "l"(p), "f"(v.x), "f"(v.y), "f"(v.z), "f"(v.w) : "memory");
}

// ---------------- setup kernels ----------------
__global__ void k_init() {
    int idx = blockIdx.x * blockDim.x + threadIdx.x;
    int stride = gridDim.x * blockDim.x;
    for (int i = idx; i < N_NODES; i += stride) d_deg[i] = 1;           // self loop
    for (int i = idx; i < 4 * 2 * HID; i += stride) d_stat[i] = 0.f;
    for (int i = idx; i < N_GRAPHS * HID; i += stride) d_pool[i] = 0.f;
    for (int i = idx; i < N_GRAPHS; i += stride) d_pcnt[i] = 0.f;
}

__global__ void k_deg(const int* __restrict__ col) {
    int idx = blockIdx.x * blockDim.x + threadIdx.x;
    int stride = gridDim.x * blockDim.x;
    for (int e = idx; e < N_EDGES; e += stride)
        atomicAdd(&d_deg[col[e]], 1);
}

__global__ void k_scanA() {
    __shared__ int s[SCAN_B];
    int i = blockIdx.x * SCAN_B + threadIdx.x;
    int v = (i < N_NODES) ? d_deg[i] - 1 : 0;
    s[threadIdx.x] = v;
    __syncthreads();
    for (int off = 1; off < SCAN_B; off <<= 1) {
        int t = (threadIdx.x >= off) ? s[threadIdx.x - off] : 0;
        __syncthreads();
        s[threadIdx.x] += t;
        __syncthreads();
    }
    if (i < N_NODES) d_off[i] = s[threadIdx.x] - v;
    if (threadIdx.x == SCAN_B - 1) d_bsum[blockIdx.x] = s[SCAN_B - 1];
}

__global__ void k_scanB() {
    __shared__ int s[256];
    int v = (threadIdx.x < NBLK) ? d_bsum[threadIdx.x] : 0;
    s[threadIdx.x] = v;
    __syncthreads();
    for (int off = 1; off < 256; off <<= 1) {
        int t = (threadIdx.x >= off) ? s[threadIdx.x - off] : 0;
        __syncthreads();
        s[threadIdx.x] += t;
        __syncthreads();
    }
    if (threadIdx.x < NBLK) d_bsum[threadIdx.x] = s[threadIdx.x] - v;
}

// scanC + dinv fused
__global__ void k_scanC() {
    int i = blockIdx.x * blockDim.x + threadIdx.x;
    if (i < N_NODES) {
        int o = d_off[i] + d_bsum[i / SCAN_B];
        d_off[i] = o;
        d_cur[i] = o;
        d_dinv[i] = rsqrtf((float)d_deg[i]);
    }
}

__global__ void k_fill(const int* __restrict__ row, const int* __restrict__ col) {
    int idx = blockIdx.x * blockDim.x + threadIdx.x;
    int stride = gridDim.x * blockDim.x;
    for (int e = idx; e < N_EDGES; e += stride) {
        int pos = atomicAdd(&d_cur[col[e]], 1);
        d_csr[pos] = row[e];
    }
}

// ---------------- GEMM ----------------
// DINV: fold dinv[n] into output (layers 1,2). Layer 0 writes raw h (no graph dep).
// TRANS: input is d_acc of prev layer: v = relu(y*s[k] + t[k])
template <int KT, bool TRANS, bool DINV>
__global__ void k_gemm(const float* __restrict__ in, const float* __restrict__ W, int stL) {
    __shared__ float sW[64 * 64];       // sW[k][f]
    __shared__ float sX[64 * 68];       // sX[k][n], padded
    const int tr = threadIdx.x & 15;
    const int tc = threadIdx.x >> 4;
    const int base = blockIdx.x * 64;
    const float* sv = d_st + stL * 128;

    float acc[4][4];
#pragma unroll
    for (int i = 0; i < 4; i++)
#pragma unroll
        for (int j = 0; j < 4; j++) acc[i][j] = 0.f;

    for (int kt = 0; kt < KT; kt++) {
        for (int i = threadIdx.x; i < 4096; i += 256)
            sW[i] = W[kt * 4096 + i];
        for (int i = threadIdx.x; i < 4096; i += 256) {
            int n = i >> 6, k = i & 63;
            int ng = base + n;
            float v = 0.f;
            if (ng < N_NODES) {
                if (TRANS) v = fmaxf(fmaf(d_acc[ng * 64 + k], sv[k], sv[64 + k]), 0.f);
                else       v = in[ng * (KT * 64) + kt * 64 + k];
            }
            sX[k * 68 + n] = v;
        }
        __syncthreads();
#pragma unroll 8
        for (int kk = 0; kk < 64; kk++) {
            float4 xv = *reinterpret_cast<float4*>(&sX[kk * 68 + tr * 4]);
            float4 wv = *reinterpret_cast<float4*>(&sW[kk * 64 + tc * 4]);
            acc[0][0] = fmaf(xv.x, wv.x, acc[0][0]);
            acc[0][1] = fmaf(xv.x, wv.y, acc[0][1]);
            acc[0][2] = fmaf(xv.x, wv.z, acc[0][2]);
            acc[0][3] = fmaf(xv.x, wv.w, acc[0][3]);
            acc[1][0] = fmaf(xv.y, wv.x, acc[1][0]);
            acc[1][1] = fmaf(xv.y, wv.y, acc[1][1]);
            acc[1][2] = fmaf(xv.y, wv.z, acc[1][2]);
            acc[1][3] = fmaf(xv.y, wv.w, acc[1][3]);
            acc[2][0] = fmaf(xv.z, wv.x, acc[2][0]);
            acc[2][1] = fmaf(xv.z, wv.y, acc[2][1]);
            acc[2][2] = fmaf(xv.z, wv.z, acc[2][2]);
            acc[2][3] = fmaf(xv.z, wv.w, acc[2][3]);
            acc[3][0] = fmaf(xv.w, wv.x, acc[3][0]);
            acc[3][1] = fmaf(xv.w, wv.y, acc[3][1]);
            acc[3][2] = fmaf(xv.w, wv.z, acc[3][2]);
            acc[3][3] = fmaf(xv.w, wv.w, acc[3][3]);
        }
        __syncthreads();
    }
#pragma unroll
    for (int i = 0; i < 4; i++) {
        int n = base + tr * 4 + i;
        if (n < N_NODES) {
            float dv = DINV ? d_dinv[n] : 1.0f;
            float4 o = make_float4(acc[i][0] * dv, acc[i][1] * dv,
                                   acc[i][2] * dv, acc[i][3] * dv);
            *reinterpret_cast<float4*>(&d_gbuf[n * 64 + tc * 4]) = o;
        }
    }
}

// ---------------- CSR gather-aggregate + fused BN stats ---------------------
// ROWDINV (layer0): gbuf holds raw h; multiply dinv[row] per gathered message.
// Otherwise gbuf already holds dinv*h.
// y[c] = dinv[c] * ( sum_msgs + self )  -> d_acc ; block-reduced sum/sumsq -> d_stat[L]
template <bool ROWDINV>
__global__ void k_aggr2(int L) {
    __shared__ float ssum[16 * 65];
    __shared__ float ssq [16 * 65];
    int w = threadIdx.x >> 5;
    int lane = threadIdx.x & 31;
    int node = blockIdx.x * 16 + w;
    const float2* gb = reinterpret_cast<const float2*>(d_gbuf);

    float2 y = {0.f, 0.f};
    if (node < N_NODES) {
        int start = d_off[node];
        int deg = d_deg[node] - 1;
        float2 a0 = {0.f,0.f}, a1 = {0.f,0.f}, a2 = {0.f,0.f}, a3 = {0.f,0.f};
        for (int base = 0; base < deg; base += 32) {
            int rem = deg - base; if (rem > 32) rem = 32;
            int id = (lane < rem) ? __ldg(&d_csr[start + base + lane]) : 0;
            float dvl = (ROWDINV && lane < rem) ? __ldg(&d_dinv[id]) : 0.f;
            int j = 0;
            for (; j + 4 <= rem; j += 4) {
                int r0 = __shfl_sync(0xffffffffu, id, j);
                int r1 = __shfl_sync(0xffffffffu, id, j + 1);
                int r2 = __shfl_sync(0xffffffffu, id, j + 2);
                int r3 = __shfl_sync(0xffffffffu, id, j + 3);
                float2 v0 = gb[r0 * 32 + lane];
                float2 v1 = gb[r1 * 32 + lane];
                float2 v2 = gb[r2 * 32 + lane];
                float2 v3 = gb[r3 * 32 + lane];
                if (ROWDINV) {
                    float d0 = __shfl_sync(0xffffffffu, dvl, j);
                    float d1 = __shfl_sync(0xffffffffu, dvl, j + 1);
                    float d2 = __shfl_sync(0xffffffffu, dvl, j + 2);
                    float d3 = __shfl_sync(0xffffffffu, dvl, j + 3);
                    a0.x = fmaf(d0, v0.x, a0.x); a0.y = fmaf(d0, v0.y, a0.y);
                    a1.x = fmaf(d1, v1.x, a1.x); a1.y = fmaf(d1, v1.y, a1.y);
                    a2.x = fmaf(d2, v2.x, a2.x); a2.y = fmaf(d2, v2.y, a2.y);
                    a3.x = fmaf(d3, v3.x, a3.x); a3.y = fmaf(d3, v3.y, a3.y);
                } else {
                    a0.x += v0.x; a0.y += v0.y;
                    a1.x += v1.x; a1.y += v1.y;
                    a2.x += v2.x; a2.y += v2.y;
                    a3.x += v3.x; a3.y += v3.y;
                }
            }
            for (; j < rem; j++) {
                int r = __shfl_sync(0xffffffffu, id, j);
                float2 v = gb[r * 32 + lane];
                if (ROWDINV) {
                    float dr = __shfl_sync(0xffffffffu, dvl, j);
                    a0.x = fmaf(dr, v.x, a0.x); a0.y = fmaf(dr, v.y, a0.y);
                } else {
                    a0.x += v.x; a0.y += v.y;
                }
            }
        }
        float dv = d_dinv[node];
        float2 self = gb[node * 32 + lane];
        float selfs = ROWDINV ? dv : 1.0f;
        y.x = (a0.x + a1.x + a2.x + a3.x + selfs * self.x) * dv;
        y.y = (a0.y + a1.y + a2.y + a3.y + selfs * self.y) * dv;
        reinterpret_cast<float2*>(d_acc)[node * 32 + lane] = y;
    }

    // fused BN stats (zeros for out-of-range nodes are harmless)
    ssum[w * 65 + 2 * lane]     = y.x;
    ssum[w * 65 + 2 * lane + 1] = y.y;
    ssq [w * 65 + 2 * lane]     = y.x * y.x;
    ssq [w * 65 + 2 * lane + 1] = y.y * y.y;
    __syncthreads();
    if (threadIdx.x < 128) {
        int feat = threadIdx.x & 63;
        bool isq = threadIdx.x >= 64;
        const float* src = isq ? ssq : ssum;
        float acc = 0.f;
#pragma unroll
        for (int ww = 0; ww < 16; ww++) acc += src[ww * 65 + feat];
        atomicAdd(&d_stat[L * 128 + (isq ? 64 : 0) + feat], acc);
    }
}

__global__ void k_fin(int L, const float* __restrict__ g, const float* __restrict__ be, float cnt) {
    int f = threadIdx.x;
    float mean = d_stat[L * 128 + f] / cnt;
    float var  = d_stat[L * 128 + 64 + f] / cnt - mean * mean;
    var = fmaxf(var, 0.f);
    float s = g[f] * rsqrtf(var + EPS);
    d_st[L * 128 + f] = s;
    d_st[L * 128 + 64 + f] = be[f] - mean * s;
}

// ---------------- pooling + head ----------------
__global__ void k_pool(const int* __restrict__ batch) {
    int t = blockIdx.x * blockDim.x + threadIdx.x;
    int lane = t & 15;
    int n = t >> 4;
    if (n >= N_NODES) return;
    int b = batch[n];
    const float* s = d_st + 2 * 128;
    float4 a = *reinterpret_cast<const float4*>(&d_acc[n * 64 + lane * 4]);
    float4 z;
    z.x = fmaxf(fmaf(a.x, s[lane * 4 + 0], s[64 + lane * 4 + 0]), 0.f);
    z.y = fmaxf(fmaf(a.y, s[lane * 4 + 1], s[64 + lane * 4 + 1]), 0.f);
    z.z = fmaxf(fmaf(a.z, s[lane * 4 + 2], s[64 + lane * 4 + 2]), 0.f);
    z.w = fmaxf(fmaf(a.w, s[lane * 4 + 3], s[64 + lane * 4 + 3]), 0.f);
    red_add_v4(&d_pool[b * 64 + lane * 4], z);
    if (lane == 0) atomicAdd(&d_pcnt[b], 1.0f);
}

__global__ void k_fc1(const float* __restrict__ W1) {
    __shared__ float sp[64];
    int gidx = blockIdx.x, f = threadIdx.x;
    float cnt = fmaxf(d_pcnt[gidx], 1.f);
    sp[f] = d_pool[gidx * 64 + f] / cnt;
    __syncthreads();
    float q = 0.f;
#pragma unroll 8
    for (int k = 0; k < 64; k++)
        q = fmaf(sp[k], __ldg(&W1[k * 64 + f]), q);
    d_q[gidx * 64 + f] = q;
    atomicAdd(&d_stat[3 * 128 + f], q);
    atomicAdd(&d_stat[3 * 128 + 64 + f], q * q);
}

__global__ void k_fc2(const float* __restrict__ W2, const float* __restrict__ b2,
                      float* __restrict__ out) {
    int g = blockIdx.x * (blockDim.x / 32) + (threadIdx.x >> 5);
    int lane = threadIdx.x & 31;
    if (g >= N_GRAPHS) return;
    const float* s = d_st + 3 * 128;
    float acc = 0.f;
#pragma unroll
    for (int j = 0; j < 2; j++) {
        int f = lane + 32 * j;
        float z = fmaxf(fmaf(d_q[g * 64 + f], s[f], s[64 + f]), 0.f);
        acc = fmaf(z, W2[f], acc);
    }
#pragma unroll
    for (int o = 16; o > 0; o >>= 1)
        acc += __shfl_down_sync(0xffffffffu, acc, o);
    if (lane == 0) out[g] = acc + b2[0];
}

// ---------------- launch ----------------
extern "C" void kernel_launch(void* const* d_in, const int* in_sizes, int n_in,
                              void* d_out, int out_size) {
    const float* x     = (const float*)d_in[0];
    const int*   ei    = (const int*)d_in[1];
    const int*   row   = ei;
    const int*   col   = ei + N_EDGES;
    const int*   batch = (const int*)d_in[2];
    const float* Wc0 = (const float*)d_in[3];
    const float* g0  = (const float*)d_in[5];
    const float* be0 = (const float*)d_in[6];
    const float* Wc1 = (const float*)d_in[7];
    const float* g1  = (const float*)d_in[9];
    const float* be1 = (const float*)d_in[10];
    const float* Wc2 = (const float*)d_in[11];
    const float* g2  = (const float*)d_in[13];
    const float* be2 = (const float*)d_in[14];
    const float* W1  = (const float*)d_in[15];
    const float* gf  = (const float*)d_in[17];
    const float* bf  = (const float*)d_in[18];
    const float* W2  = (const float*)d_in[19];
    const float* b2  = (const float*)d_in[20];
    float* out = (float*)d_out;

    // persistent side stream + events (host resources; created once, reused)
    static cudaStream_t s1 = nullptr;
    static cudaEvent_t eFork = nullptr, eGemm0 = nullptr;
    if (s1 == nullptr) {
        cudaStreamCreateWithFlags(&s1, cudaStreamNonBlocking);
        cudaEventCreateWithFlags(&eFork, cudaEventDisableTiming);
        cudaEventCreateWithFlags(&eGemm0, cudaEventDisableTiming);
    }

    const int GEMM_GRID = (N_NODES + 63) / 64;              // 1563
    const int AGGR_GRID = (N_NODES + 15) / 16;              // 6250 (512 thr)
    const int POOL_GRID = (N_NODES * 16 + 255) / 256;       // 6250

    // Fork: GEMM0 (x @ Wc0, no graph dependency) runs on s1 in parallel with
    // the CSR build chain on the origin stream.
    cudaEventRecord(eFork, 0);
    cudaStreamWaitEvent(s1, eFork, 0);
    k_gemm<2, false, false><<<GEMM_GRID, 256, 0, s1>>>(x, Wc0, 0);
    cudaEventRecord(eGemm0, s1);

    k_init<<<1024, 256>>>();
    k_deg <<<8192, 256>>>(col);
    k_scanA<<<NBLK, SCAN_B>>>();
    k_scanB<<<1, 256>>>();
    k_scanC<<<(N_NODES + 255) / 256, 256>>>();
    k_fill<<<8192, 256>>>(row, col);

    cudaStreamWaitEvent(0, eGemm0, 0);

    // layer 0 (gbuf = raw h; dinv[row] applied in gather)
    k_aggr2<true><<<AGGR_GRID, 512>>>(0);
    k_fin<<<1, 64>>>(0, g0, be0, (float)N_NODES);

    // layer 1
    k_gemm<1, true, true><<<GEMM_GRID, 256>>>(x, Wc1, 0);
    k_aggr2<false><<<AGGR_GRID, 512>>>(1);
    k_fin<<<1, 64>>>(1, g1, be1, (float)N_NODES);

    // layer 2
    k_gemm<1, true, true><<<GEMM_GRID, 256>>>(x, Wc2, 1);
    k_aggr2<false><<<AGGR_GRID, 512>>>(2);
    k_fin<<<1, 64>>>(2, g2, be2, (float)N_NODES);

    // pooling + head
    k_pool<<<POOL_GRID, 256>>>(batch);
    k_fc1<<<N_GRAPHS, 64>>>(W1);
    k_fin<<<1, 64>>>(3, gf, bf, (float)N_GRAPHS);
    k_fc2<<<N_GRAPHS / 8, 256>>>(W2, b2, out);
}

// round 4
// speedup vs baseline: 1.8443x; 1.1024x over previous
#include <cuda_runtime.h>
#include <cuda_fp16.h>

#define N_NODES 100000
#define N_EDGES 3200000
#define N_GRAPHS 4096
#define IN_DIM 128
#define HID 64
#define EPS 1e-5f

#define SCAN_B 512
#define NBLK ((N_NODES + SCAN_B - 1) / SCAN_B)   // 196

// ---------------- scratch (device globals; no allocation) ----------------
__device__ __half2 d_gh [N_NODES * 32];   // fp16 messages (layer0: h; layers1/2: dinv*h)
__device__ float   d_acc[N_NODES * HID];  // conv output y (post-dinv, pre-BN) fp32
__device__ int     d_deg [N_NODES];
__device__ float   d_dinv[N_NODES];
__device__ int     d_off [N_NODES];
__device__ int     d_cur [N_NODES];
__device__ int     d_bsum[NBLK];
__device__ int     d_csr [N_EDGES];
__device__ float   d_stat[4 * 2 * HID];
__device__ float   d_pool[N_GRAPHS * HID];
__device__ float   d_pcnt[N_GRAPHS];
__device__ float   d_q   [N_GRAPHS * HID];

__device__ __forceinline__ void red_add_v4(float* addr, float4 v) {
    unsigned long long p = (unsigned long long)__cvta_generic_to_global(addr);
    asm volatile("red.global.add.v4.f32 [%0], {%1,%2,%3,%4};"
                 :: "l"(p), "f"(v.x), "f"(v.y), "f"(v.z), "f"(v.w) : "memory");
}

// compute BN scale/shift for layer L into shared arrays (first 64 threads)
__device__ __forceinline__ void bn_to_smem(int L, const float* g, const float* be,
                                           float cnt, float* sS, float* sT) {
    if (threadIdx.x < 64) {
        int f = threadIdx.x;
        float mean = d_stat[L * 128 + f] / cnt;
        float var  = d_stat[L * 128 + 64 + f] / cnt - mean * mean;
        var = fmaxf(var, 0.f);
        float s = g[f] * rsqrtf(var + EPS);
        sS[f] = s;
        sT[f] = be[f] - mean * s;
    }
    __syncthreads();
}

// ---------------- setup kernels ----------------
__global__ void k_init() {
    int idx = blockIdx.x * blockDim.x + threadIdx.x;
    int stride = gridDim.x * blockDim.x;
    for (int i = idx; i < N_NODES; i += stride) d_deg[i] = 1;           // self loop
    for (int i = idx; i < 4 * 2 * HID; i += stride) d_stat[i] = 0.f;
    for (int i = idx; i < N_GRAPHS * HID; i += stride) d_pool[i] = 0.f;
    for (int i = idx; i < N_GRAPHS; i += stride) d_pcnt[i] = 0.f;
}

__global__ void k_deg(const int* __restrict__ col) {
    int idx = blockIdx.x * blockDim.x + threadIdx.x;
    int stride = gridDim.x * blockDim.x;
    for (int e = idx; e < N_EDGES; e += stride)
        atomicAdd(&d_deg[col[e]], 1);
}

__global__ void k_scanA() {
    __shared__ int s[SCAN_B];
    int i = blockIdx.x * SCAN_B + threadIdx.x;
    int v = (i < N_NODES) ? d_deg[i] - 1 : 0;
    s[threadIdx.x] = v;
    __syncthreads();
    for (int off = 1; off < SCAN_B; off <<= 1) {
        int t = (threadIdx.x >= off) ? s[threadIdx.x - off] : 0;
        __syncthreads();
        s[threadIdx.x] += t;
        __syncthreads();
    }
    if (i < N_NODES) d_off[i] = s[threadIdx.x] - v;
    if (threadIdx.x == SCAN_B - 1) d_bsum[blockIdx.x] = s[SCAN_B - 1];
}

__global__ void k_scanB() {
    __shared__ int s[256];
    int v = (threadIdx.x < NBLK) ? d_bsum[threadIdx.x] : 0;
    s[threadIdx.x] = v;
    __syncthreads();
    for (int off = 1; off < 256; off <<= 1) {
        int t = (threadIdx.x >= off) ? s[threadIdx.x - off] : 0;
        __syncthreads();
        s[threadIdx.x] += t;
        __syncthreads();
    }
    if (threadIdx.x < NBLK) d_bsum[threadIdx.x] = s[threadIdx.x] - v;
}

__global__ void k_scanC() {
    int i = blockIdx.x * blockDim.x + threadIdx.x;
    if (i < N_NODES) {
        int o = d_off[i] + d_bsum[i / SCAN_B];
        d_off[i] = o;
        d_cur[i] = o;
        d_dinv[i] = rsqrtf((float)d_deg[i]);
    }
}

__global__ void k_fill(const int* __restrict__ row, const int* __restrict__ col) {
    int idx = blockIdx.x * blockDim.x + threadIdx.x;
    int stride = gridDim.x * blockDim.x;
    for (int e = idx; e < N_EDGES; e += stride) {
        int pos = atomicAdd(&d_cur[col[e]], 1);
        d_csr[pos] = row[e];
    }
}

// ---------------- GEMM ----------------
// Output: d_gh[n][f] (fp16), = (dinv[n] if DINV) * sum_k v[n][k] * W[k][f]
// TRANS: v = relu(BN(d_acc)) with BN params computed from d_stat[stL] in-block.
template <int KT, bool TRANS, bool DINV>
__global__ void k_gemm(const float* __restrict__ in, const float* __restrict__ W,
                       int stL, const float* __restrict__ g, const float* __restrict__ be,
                       float cnt) {
    __shared__ float sW[64 * 64];       // sW[k][f]
    __shared__ float sX[64 * 68];       // sX[k][n], padded
    __shared__ float sS[64], sT[64];
    const int tr = threadIdx.x & 15;
    const int tc = threadIdx.x >> 4;
    const int base = blockIdx.x * 64;

    if (TRANS) bn_to_smem(stL, g, be, cnt, sS, sT);

    float acc[4][4];
#pragma unroll
    for (int i = 0; i < 4; i++)
#pragma unroll
        for (int j = 0; j < 4; j++) acc[i][j] = 0.f;

    for (int kt = 0; kt < KT; kt++) {
        for (int i = threadIdx.x; i < 4096; i += 256)
            sW[i] = W[kt * 4096 + i];
        for (int i = threadIdx.x; i < 4096; i += 256) {
            int n = i >> 6, k = i & 63;
            int ng = base + n;
            float v = 0.f;
            if (ng < N_NODES) {
                if (TRANS) v = fmaxf(fmaf(d_acc[ng * 64 + k], sS[k], sT[k]), 0.f);
                else       v = in[ng * (KT * 64) + kt * 64 + k];
            }
            sX[k * 68 + n] = v;
        }
        __syncthreads();
#pragma unroll 8
        for (int kk = 0; kk < 64; kk++) {
            float4 xv = *reinterpret_cast<float4*>(&sX[kk * 68 + tr * 4]);
            float4 wv = *reinterpret_cast<float4*>(&sW[kk * 64 + tc * 4]);
            acc[0][0] = fmaf(xv.x, wv.x, acc[0][0]);
            acc[0][1] = fmaf(xv.x, wv.y, acc[0][1]);
            acc[0][2] = fmaf(xv.x, wv.z, acc[0][2]);
            acc[0][3] = fmaf(xv.x, wv.w, acc[0][3]);
            acc[1][0] = fmaf(xv.y, wv.x, acc[1][0]);
            acc[1][1] = fmaf(xv.y, wv.y, acc[1][1]);
            acc[1][2] = fmaf(xv.y, wv.z, acc[1][2]);
            acc[1][3] = fmaf(xv.y, wv.w, acc[1][3]);
            acc[2][0] = fmaf(xv.z, wv.x, acc[2][0]);
            acc[2][1] = fmaf(xv.z, wv.y, acc[2][1]);
            acc[2][2] = fmaf(xv.z, wv.z, acc[2][2]);
            acc[2][3] = fmaf(xv.z, wv.w, acc[2][3]);
            acc[3][0] = fmaf(xv.w, wv.x, acc[3][0]);
            acc[3][1] = fmaf(xv.w, wv.y, acc[3][1]);
            acc[3][2] = fmaf(xv.w, wv.z, acc[3][2]);
            acc[3][3] = fmaf(xv.w, wv.w, acc[3][3]);
        }
        __syncthreads();
    }
#pragma unroll
    for (int i = 0; i < 4; i++) {
        int n = base + tr * 4 + i;
        if (n < N_NODES) {
            float dv = DINV ? d_dinv[n] : 1.0f;
            __half2 h0 = __floats2half2_rn(acc[i][0] * dv, acc[i][1] * dv);
            __half2 h1 = __floats2half2_rn(acc[i][2] * dv, acc[i][3] * dv);
            uint2 u;
            u.x = *reinterpret_cast<unsigned*>(&h0);
            u.y = *reinterpret_cast<unsigned*>(&h1);
            *reinterpret_cast<uint2*>(&d_gh[n * 32 + tc * 2]) = u;
        }
    }
}

// ---------------- CSR gather-aggregate + fused BN stats ---------------------
// y[c] = dinv[c]*( sum_{e:col=c} (dinv[row] if ROWDINV)*g[row] + (dinv[c] if ROWDINV)*g[c] )
template <bool ROWDINV>
__global__ void k_aggr2(int L) {
    __shared__ float ssum[16 * 65];
    __shared__ float ssq [16 * 65];
    int w = threadIdx.x >> 5;
    int lane = threadIdx.x & 31;
    int node = blockIdx.x * 16 + w;

    float2 y = {0.f, 0.f};
    if (node < N_NODES) {
        int start = d_off[node];
        int deg = d_deg[node] - 1;
        float2 a0 = {0.f,0.f}, a1 = {0.f,0.f}, a2 = {0.f,0.f}, a3 = {0.f,0.f};
        for (int base = 0; base < deg; base += 32) {
            int rem = deg - base; if (rem > 32) rem = 32;
            int id = (lane < rem) ? __ldg(&d_csr[start + base + lane]) : 0;
            float dvl = (ROWDINV && lane < rem) ? __ldg(&d_dinv[id]) : 0.f;
            int j = 0;
            for (; j + 4 <= rem; j += 4) {
                int r0 = __shfl_sync(0xffffffffu, id, j);
                int r1 = __shfl_sync(0xffffffffu, id, j + 1);
                int r2 = __shfl_sync(0xffffffffu, id, j + 2);
                int r3 = __shfl_sync(0xffffffffu, id, j + 3);
                float2 v0 = __half22float2(d_gh[r0 * 32 + lane]);
                float2 v1 = __half22float2(d_gh[r1 * 32 + lane]);
                float2 v2 = __half22float2(d_gh[r2 * 32 + lane]);
                float2 v3 = __half22float2(d_gh[r3 * 32 + lane]);
                if (ROWDINV) {
                    float dd0 = __shfl_sync(0xffffffffu, dvl, j);
                    float dd1 = __shfl_sync(0xffffffffu, dvl, j + 1);
                    float dd2 = __shfl_sync(0xffffffffu, dvl, j + 2);
                    float dd3 = __shfl_sync(0xffffffffu, dvl, j + 3);
                    a0.x = fmaf(dd0, v0.x, a0.x); a0.y = fmaf(dd0, v0.y, a0.y);
                    a1.x = fmaf(dd1, v1.x, a1.x); a1.y = fmaf(dd1, v1.y, a1.y);
                    a2.x = fmaf(dd2, v2.x, a2.x); a2.y = fmaf(dd2, v2.y, a2.y);
                    a3.x = fmaf(dd3, v3.x, a3.x); a3.y = fmaf(dd3, v3.y, a3.y);
                } else {
                    a0.x += v0.x; a0.y += v0.y;
                    a1.x += v1.x; a1.y += v1.y;
                    a2.x += v2.x; a2.y += v2.y;
                    a3.x += v3.x; a3.y += v3.y;
                }
            }
            for (; j < rem; j++) {
                int r = __shfl_sync(0xffffffffu, id, j);
                float2 v = __half22float2(d_gh[r * 32 + lane]);
                if (ROWDINV) {
                    float dr = __shfl_sync(0xffffffffu, dvl, j);
                    a0.x = fmaf(dr, v.x, a0.x); a0.y = fmaf(dr, v.y, a0.y);
                } else {
                    a0.x += v.x; a0.y += v.y;
                }
            }
        }
        float dv = d_dinv[node];
        float2 self = __half22float2(d_gh[node * 32 + lane]);
        float selfs = ROWDINV ? dv : 1.0f;
        y.x = (a0.x + a1.x + a2.x + a3.x + selfs * self.x) * dv;
        y.y = (a0.y + a1.y + a2.y + a3.y + selfs * self.y) * dv;
        reinterpret_cast<float2*>(d_acc)[node * 32 + lane] = y;
    }

    ssum[w * 65 + 2 * lane]     = y.x;
    ssum[w * 65 + 2 * lane + 1] = y.y;
    ssq [w * 65 + 2 * lane]     = y.x * y.x;
    ssq [w * 65 + 2 * lane + 1] = y.y * y.y;
    __syncthreads();
    if (threadIdx.x < 128) {
        int feat = threadIdx.x & 63;
        bool isq = threadIdx.x >= 64;
        const float* src = isq ? ssq : ssum;
        float acc = 0.f;
#pragma unroll
        for (int ww = 0; ww < 16; ww++) acc += src[ww * 65 + feat];
        atomicAdd(&d_stat[L * 128 + (isq ? 64 : 0) + feat], acc);
    }
}

// ---------------- pooling + head ----------------
__global__ void k_pool(const int* __restrict__ batch,
                       const float* __restrict__ g, const float* __restrict__ be) {
    __shared__ float sS[64], sT[64];
    bn_to_smem(2, g, be, (float)N_NODES, sS, sT);
    int t = blockIdx.x * blockDim.x + threadIdx.x;
    int lane = t & 15;
    int n = t >> 4;
    if (n >= N_NODES) return;
    int b = batch[n];
    float4 a = *reinterpret_cast<const float4*>(&d_acc[n * 64 + lane * 4]);
    float4 z;
    z.x = fmaxf(fmaf(a.x, sS[lane * 4 + 0], sT[lane * 4 + 0]), 0.f);
    z.y = fmaxf(fmaf(a.y, sS[lane * 4 + 1], sT[lane * 4 + 1]), 0.f);
    z.z = fmaxf(fmaf(a.z, sS[lane * 4 + 2], sT[lane * 4 + 2]), 0.f);
    z.w = fmaxf(fmaf(a.w, sS[lane * 4 + 3], sT[lane * 4 + 3]), 0.f);
    red_add_v4(&d_pool[b * 64 + lane * 4], z);
    if (lane == 0) atomicAdd(&d_pcnt[b], 1.0f);
}

__global__ void k_fc1(const float* __restrict__ W1) {
    __shared__ float sp[64];
    int gidx = blockIdx.x, f = threadIdx.x;
    float cnt = fmaxf(d_pcnt[gidx], 1.f);
    sp[f] = d_pool[gidx * 64 + f] / cnt;
    __syncthreads();
    float q = 0.f;
#pragma unroll 8
    for (int k = 0; k < 64; k++)
        q = fmaf(sp[k], __ldg(&W1[k * 64 + f]), q);
    d_q[gidx * 64 + f] = q;
    atomicAdd(&d_stat[3 * 128 + f], q);
    atomicAdd(&d_stat[3 * 128 + 64 + f], q * q);
}

__global__ void k_fc2(const float* __restrict__ W2, const float* __restrict__ b2,
                      const float* __restrict__ gf, const float* __restrict__ bf,
                      float* __restrict__ out) {
    __shared__ float sS[64], sT[64];
    bn_to_smem(3, gf, bf, (float)N_GRAPHS, sS, sT);
    int g = blockIdx.x * (blockDim.x / 32) + (threadIdx.x >> 5);
    int lane = threadIdx.x & 31;
    if (g >= N_GRAPHS) return;
    float acc = 0.f;
#pragma unroll
    for (int j = 0; j < 2; j++) {
        int f = lane + 32 * j;
        float z = fmaxf(fmaf(d_q[g * 64 + f], sS[f], sT[f]), 0.f);
        acc = fmaf(z, W2[f], acc);
    }
#pragma unroll
    for (int o = 16; o > 0; o >>= 1)
        acc += __shfl_down_sync(0xffffffffu, acc, o);
    if (lane == 0) out[g] = acc + b2[0];
}

// ---------------- launch ----------------
extern "C" void kernel_launch(void* const* d_in, const int* in_sizes, int n_in,
                              void* d_out, int out_size) {
    const float* x     = (const float*)d_in[0];
    const int*   ei    = (const int*)d_in[1];
    const int*   row   = ei;
    const int*   col   = ei + N_EDGES;
    const int*   batch = (const int*)d_in[2];
    const float* Wc0 = (const float*)d_in[3];
    const float* g0  = (const float*)d_in[5];
    const float* be0 = (const float*)d_in[6];
    const float* Wc1 = (const float*)d_in[7];
    const float* g1  = (const float*)d_in[9];
    const float* be1 = (const float*)d_in[10];
    const float* Wc2 = (const float*)d_in[11];
    const float* g2  = (const float*)d_in[13];
    const float* be2 = (const float*)d_in[14];
    const float* W1  = (const float*)d_in[15];
    const float* gf  = (const float*)d_in[17];
    const float* bf  = (const float*)d_in[18];
    const float* W2  = (const float*)d_in[19];
    const float* b2  = (const float*)d_in[20];
    float* out = (float*)d_out;

    static cudaStream_t s1 = nullptr;
    static cudaEvent_t eFork = nullptr, eGemm0 = nullptr;
    if (s1 == nullptr) {
        cudaStreamCreateWithFlags(&s1, cudaStreamNonBlocking);
        cudaEventCreateWithFlags(&eFork, cudaEventDisableTiming);
        cudaEventCreateWithFlags(&eGemm0, cudaEventDisableTiming);
    }

    const int GEMM_GRID = (N_NODES + 63) / 64;              // 1563
    const int AGGR_GRID = (N_NODES + 15) / 16;              // 6250 (512 thr)
    const int POOL_GRID = (N_NODES * 16 + 255) / 256;       // 6250

    // Fork: GEMM0 (x @ Wc0, no graph dependency) overlaps the CSR build chain.
    cudaEventRecord(eFork, 0);
    cudaStreamWaitEvent(s1, eFork, 0);
    k_gemm<2, false, false><<<GEMM_GRID, 256, 0, s1>>>(x, Wc0, 0, nullptr, nullptr, 1.f);
    cudaEventRecord(eGemm0, s1);

    k_init<<<1024, 256>>>();
    k_deg <<<8192, 256>>>(col);
    k_scanA<<<NBLK, SCAN_B>>>();
    k_scanB<<<1, 256>>>();
    k_scanC<<<(N_NODES + 255) / 256, 256>>>();
    k_fill<<<8192, 256>>>(row, col);

    cudaStreamWaitEvent(0, eGemm0, 0);

    // layer 0 (gh = raw h in fp16; dinv[row] applied in gather)
    k_aggr2<true><<<AGGR_GRID, 512>>>(0);

    // layer 1 (BN(0) computed inside gemm)
    k_gemm<1, true, true><<<GEMM_GRID, 256>>>(x, Wc1, 0, g0, be0, (float)N_NODES);
    k_aggr2<false><<<AGGR_GRID, 512>>>(1);

    // layer 2
    k_gemm<1, true, true><<<GEMM_GRID, 256>>>(x, Wc2, 1, g1, be1, (float)N_NODES);
    k_aggr2<false><<<AGGR_GRID, 512>>>(2);

    // pooling + head (BN(2) inside pool, BN(3) inside fc2)
    k_pool<<<POOL_GRID, 256>>>(batch, g2, be2);
    k_fc1<<<N_GRAPHS, 64>>>(W1);
    k_fc2<<<N_GRAPHS / 8, 256>>>(W2, b2, gf, bf, out);
}